// round 10
// baseline (speedup 1.0000x reference)
#include <cuda_runtime.h>

#define BB 8
#define LL 256
#define DD 256
#define KK 64
#define IPB 4            // i-rows per block (one f32x2 pair per thread half)

#define TANH_C 2.885390081777927f   // 2*log2(e): e^(2x) = exp2(C*x)

// scratch: projections, PRE-SCALED by TANH_C
__device__ float g_qi[BB*LL*KK];    // [b][i][k]
__device__ float g_kjT[BB*KK*LL];   // [b][k][j]  (k-major for coalesced j loads)

__device__ __forceinline__ unsigned long long fma2u(unsigned long long a,
                                                    unsigned long long b,
                                                    unsigned long long c) {
    unsigned long long d;
    asm("fma.rn.f32x2 %0, %1, %2, %3;" : "=l"(d) : "l"(a), "l"(b), "l"(c));
    return d;
}
__device__ __forceinline__ unsigned long long mul2u(unsigned long long a,
                                                    unsigned long long b) {
    unsigned long long d;
    asm("mul.rn.f32x2 %0, %1, %2;" : "=l"(d) : "l"(a), "l"(b));
    return d;
}
__device__ __forceinline__ float2 u2f2(unsigned long long v) {
    float2 r;
    asm("mov.b64 {%0, %1}, %2;" : "=f"(r.x), "=f"(r.y) : "l"(v));
    return r;
}
__device__ __forceinline__ unsigned long long dupf(float v) {
    unsigned long long d;
    asm("mov.b64 %0, {%1, %1};" : "=l"(d) : "f"(v));
    return d;
}
__device__ __forceinline__ float fast_ex2(float x) {
    float y; asm("ex2.approx.f32 %0, %1;" : "=f"(y) : "f"(x)); return y;
}

// acc += wv2 * y' where y' -> -1/(1+exp2(q+kv)), per packed pair.
// Magic 0xFEF311C3: reciprocal magic with sign folded (negative guess), so
// Newton y1' = y0'*(2 + d*y0') needs no negation.
__device__ __forceinline__ void sig_acc(float q0, float q1, float kv,
                                        unsigned long long wv2,
                                        unsigned long long two2,
                                        unsigned long long& acc) {
    float t0 = q0 + kv, t1 = q1 + kv;
    float e0 = fast_ex2(t0), e1 = fast_ex2(t1);
    float d0 = e0 + 1.0f,    d1 = e1 + 1.0f;
    unsigned u0 = 0xFEF311C3u - __float_as_uint(d0);
    unsigned u1 = 0xFEF311C3u - __float_as_uint(d1);
    unsigned long long dp, yp, s;
    asm("mov.b64 %0, {%1, %2};" : "=l"(dp) : "f"(d0), "f"(d1));
    asm("mov.b64 %0, {%1, %2};" : "=l"(yp) : "r"(u0), "r"(u1));
    s = fma2u(dp, yp, two2);  yp = mul2u(yp, s);
    s = fma2u(dp, yp, two2);  yp = mul2u(yp, s);
    acc = fma2u(wv2, yp, acc);
}

// ---------------------------------------------------------------------------
// Kernel 1: qi[b,i,k] = C * x[b,i,:]·W1[k,0:256], kjT[b,k,j] = C * x[b,j,:]·W1[k,256:512]
// grid = 128 blocks, 512 threads, dynamic smem ~81 KB
// ---------------------------------------------------------------------------
#define XPAD 260   // floats per padded x row (65 float4)
#define P_XS 0
#define P_WS (16 * XPAD)
#define PROJ_SMEM_FLOATS (P_WS + 32 * 2 * DD)
#define PROJ_SMEM_BYTES  (PROJ_SMEM_FLOATS * 4)

__global__ void __launch_bounds__(512, 1)
proj_kernel(const float* __restrict__ x, const float* __restrict__ W1) {
    extern __shared__ float psm[];
    float* xs = psm + P_XS;
    float* ws = psm + P_WS;

    int b  = blockIdx.x >> 4;
    int r0 = (blockIdx.x & 15) << 4;
    int t  = threadIdx.x;

    {
        float4* xs4 = (float4*)xs;
        const float4* xg = (const float4*)(x + (b * LL + r0) * DD);
        #pragma unroll
        for (int u = t; u < 16 * DD / 4; u += 512) {
            int row = u >> 6;
            int c4  = u & 63;
            xs4[row * (XPAD / 4) + c4] = xg[u];
        }
    }

    int k = t >> 4;
    int r = t & 15;

    #pragma unroll
    for (int kc = 0; kc < KK; kc += 32) {
        __syncthreads();
        float4* ws4 = (float4*)ws;
        const float4* wg = (const float4*)(W1 + kc * 2 * DD);
        #pragma unroll
        for (int u = t; u < 32 * 2 * DD / 4; u += 512) ws4[u] = wg[u];
        __syncthreads();

        const ulonglong2* xa = (const ulonglong2*)(xs + r * XPAD);
        const ulonglong2* wi = (const ulonglong2*)(ws + k * 2 * DD);
        const ulonglong2* wj = (const ulonglong2*)(ws + k * 2 * DD + DD);

        unsigned long long aq0 = 0ull, aq1 = 0ull, ak0 = 0ull, ak1 = 0ull;
        #pragma unroll 8
        for (int d4 = 0; d4 < DD / 4; d4++) {
            ulonglong2 xv  = xa[d4];
            ulonglong2 wiv = wi[d4];
            ulonglong2 wjv = wj[d4];
            aq0 = fma2u(xv.x, wiv.x, aq0);
            aq1 = fma2u(xv.y, wiv.y, aq1);
            ak0 = fma2u(xv.x, wjv.x, ak0);
            ak1 = fma2u(xv.y, wjv.y, ak1);
        }
        float2 f;
        float qs, ks;
        f = u2f2(aq0); qs  = f.x + f.y;
        f = u2f2(aq1); qs += f.x + f.y;
        f = u2f2(ak0); ks  = f.x + f.y;
        f = u2f2(ak1); ks += f.x + f.y;

        int kk = kc + k;
        int rg = r0 + r;
        g_qi [(b * LL + rg) * KK + kk] = qs * TANH_C;
        g_kjT[(b * KK + kk) * LL + rg] = ks * TANH_C;
    }
}

// ---------------------------------------------------------------------------
// Kernel 2: fused scores + softmax + context + concat
// grid = 512 blocks (8 b x 64 i-tiles of 4), 512 threads, ~13 KB static smem,
// up to 4 blocks/SM resident (launch_bounds(512,4) -> <=32 regs).
// Thread map: tj = t&255 (j in A, d in C), p = t>>8 (i-pair 0/1).
// ---------------------------------------------------------------------------
#define ATP 8   // attnT padded row (floats)

__global__ void __launch_bounds__(512, 4)
attn_kernel(const float* __restrict__ x, const float* __restrict__ W2,
            float* __restrict__ out) {
    __shared__ float qis_t[KK * IPB];      // [k][i]  1 KB
    __shared__ float scoresS[IPB * LL];    // [i][j]  4 KB
    __shared__ float attnT[LL * ATP];      // [j][i(pad)] 8 KB
    __shared__ float w2s[KK];

    int b  = blockIdx.x >> 6;
    int i0 = (blockIdx.x & 63) * IPB;
    int t  = threadIdx.x;
    int tj = t & 255;
    int p  = t >> 8;           // i-pair index (0 or 1)

    // stage qi tile transposed + W2 pre-doubled
    if (t < KK * IPB) {
        int i = t & 3, k = t >> 2;
        qis_t[k * IPB + i] = g_qi[(b * LL + i0 + i) * KK + k];
    }
    if (t >= 512 - KK) w2s[t - (512 - KK)] = 2.0f * W2[t - (512 - KK)];
    __syncthreads();

    // ---- Phase A: score'(2p+.,j) over k; kv streamed from L2 (coalesced) ----
    unsigned long long acc = 0ull;
    unsigned long long two2 = dupf(2.0f);
    const float* kjb = g_kjT + b * KK * LL + tj;
    const float* qt  = qis_t + p * 2;

    #pragma unroll 4
    for (int k = 0; k < KK; k++) {
        float kv = __ldg(kjb + k * LL);
        unsigned long long wv2 = dupf(w2s[k]);
        float q0 = qt[k * IPB];
        float q1 = qt[k * IPB + 1];
        sig_acc(q0, q1, kv, wv2, two2, acc);
    }
    {
        float2 a = u2f2(acc);
        scoresS[(p * 2 + 0) * LL + tj] = a.x;
        scoresS[(p * 2 + 1) * LL + tj] = a.y;
    }
    __syncthreads();

    // ---- Phase B: softmax over j; warps 0-3 handle one i each ----
    if (t < 128) {
        int w = t >> 5, lane = t & 31;
        float v[8];
        float mx = -1e30f;
        #pragma unroll
        for (int r = 0; r < 8; r++) {
            v[r] = scoresS[w * LL + lane + 32 * r];
            mx = fmaxf(mx, v[r]);
        }
        #pragma unroll
        for (int o = 16; o; o >>= 1) mx = fmaxf(mx, __shfl_xor_sync(0xffffffffu, mx, o));
        float s = 0.f;
        #pragma unroll
        for (int r = 0; r < 8; r++) { v[r] = __expf(v[r] - mx); s += v[r]; }
        #pragma unroll
        for (int o = 16; o; o >>= 1) s += __shfl_xor_sync(0xffffffffu, s, o);
        float inv = 1.f / s;
        #pragma unroll
        for (int r = 0; r < 8; r++)
            attnT[(lane + 32 * r) * ATP + w] = v[r] * inv;
    }
    __syncthreads();

    // ---- Phase C: ctx[2p+.][tj] = sum_j attn * x[b,j,tj]; unroll 8 for MLP ----
    unsigned long long accp = 0ull;
    const float* xb = x + b * LL * DD;
    const float* xc = xb + tj;
    const unsigned long long* atp =
        (const unsigned long long*)(attnT + p * 2);

    #pragma unroll 8
    for (int j = 0; j < LL; j++) {
        float xv = __ldg(xc + j * DD);
        unsigned long long aa = atp[j * (ATP / 2)];   // broadcast LDS.64
        accp = fma2u(aa, dupf(xv), accp);
    }

    // ---- Output rows for this pair's 2 i's ----
    {
        float2 c = u2f2(accp);
        int ia = i0 + p * 2;
        float xv0 = xb[(i0 + p * 2) * DD + tj];
        float xv1 = xb[(i0 + p * 2 + 1) * DD + tj];
        float* row0 = out + (unsigned)(b * LL + ia) * (2 * DD);
        float* row1 = row0 + 2 * DD;
        row0[tj]      = xv0;
        row0[DD + tj] = c.x;
        row1[tj]      = xv1;
        row1[DD + tj] = c.y;
    }
}

// ---------------------------------------------------------------------------
extern "C" void kernel_launch(void* const* d_in, const int* in_sizes, int n_in,
                              void* d_out, int out_size) {
    const float* x  = (const float*)d_in[0];   // (8,256,256)
    const float* W1 = (const float*)d_in[1];   // (64,512)
    const float* W2 = (const float*)d_in[2];   // (1,64)
    float* out = (float*)d_out;                // (8,256,512)

    cudaFuncSetAttribute(proj_kernel,
                         cudaFuncAttributeMaxDynamicSharedMemorySize,
                         PROJ_SMEM_BYTES);
    proj_kernel<<<BB * (LL / 16), 512, PROJ_SMEM_BYTES>>>(x, W1);

    attn_kernel<<<BB * (LL / IPB), 512>>>(x, W2, out);
}

// round 11
// speedup vs baseline: 1.0375x; 1.0375x over previous
#include <cuda_runtime.h>

#define BB 8
#define LL 256
#define DD 256
#define KK 64
#define IPB 4            // i-rows per block

#define TANH_C 2.885390081777927f   // 2*log2(e): e^(2x) = exp2(C*x)

// scratch: projections, PRE-SCALED by TANH_C
__device__ float g_qi[BB*LL*KK];    // [b][i][k]
__device__ float g_kjT[BB*KK*LL];   // [b][k][j]  (k-major: chunk staging is contiguous)

__device__ __forceinline__ unsigned long long fma2u(unsigned long long a,
                                                    unsigned long long b,
                                                    unsigned long long c) {
    unsigned long long d;
    asm("fma.rn.f32x2 %0, %1, %2, %3;" : "=l"(d) : "l"(a), "l"(b), "l"(c));
    return d;
}
__device__ __forceinline__ unsigned long long mul2u(unsigned long long a,
                                                    unsigned long long b) {
    unsigned long long d;
    asm("mul.rn.f32x2 %0, %1, %2;" : "=l"(d) : "l"(a), "l"(b));
    return d;
}
__device__ __forceinline__ unsigned long long add2u(unsigned long long a,
                                                    unsigned long long b) {
    unsigned long long d;
    asm("add.rn.f32x2 %0, %1, %2;" : "=l"(d) : "l"(a), "l"(b));
    return d;
}
__device__ __forceinline__ float2 u2f2(unsigned long long v) {
    float2 r;
    asm("mov.b64 {%0, %1}, %2;" : "=f"(r.x), "=f"(r.y) : "l"(v));
    return r;
}
__device__ __forceinline__ unsigned long long dupf(float v) {
    unsigned long long d;
    asm("mov.b64 %0, {%1, %1};" : "=l"(d) : "f"(v));
    return d;
}
__device__ __forceinline__ float fast_ex2(float x) {
    float y; asm("ex2.approx.f32 %0, %1;" : "=f"(y) : "f"(x)); return y;
}

// acc += wv2 * y', y' -> -1/(1+exp2(q+kv)) per packed i-pair.
// Magic 0xFEF311C3: reciprocal magic with sign folded (negative guess);
// Newton y1' = y0'*(2 + d*y0') twice.
__device__ __forceinline__ void sig_acc(float q0, float q1, float kv,
                                        unsigned long long wv2,
                                        unsigned long long two2,
                                        unsigned long long& acc) {
    float t0 = q0 + kv, t1 = q1 + kv;
    float e0 = fast_ex2(t0), e1 = fast_ex2(t1);
    float d0 = e0 + 1.0f,    d1 = e1 + 1.0f;
    unsigned u0 = 0xFEF311C3u - __float_as_uint(d0);
    unsigned u1 = 0xFEF311C3u - __float_as_uint(d1);
    unsigned long long dp, yp, s;
    asm("mov.b64 %0, {%1, %2};" : "=l"(dp) : "f"(d0), "f"(d1));
    asm("mov.b64 %0, {%1, %2};" : "=l"(yp) : "r"(u0), "r"(u1));
    s = fma2u(dp, yp, two2);  yp = mul2u(yp, s);
    s = fma2u(dp, yp, two2);  yp = mul2u(yp, s);
    acc = fma2u(wv2, yp, acc);
}

// ---------------------------------------------------------------------------
// Kernel 1: qi[b,i,k] = C * x[b,i,:]·W1[k,0:256], kjT[b,k,j] = C * x[b,j,:]·W1[k,256:512]
// (unchanged from R9)
// ---------------------------------------------------------------------------
#define XPAD 260
#define P_XS 0
#define P_WS (16 * XPAD)
#define PROJ_SMEM_FLOATS (P_WS + 32 * 2 * DD)
#define PROJ_SMEM_BYTES  (PROJ_SMEM_FLOATS * 4)

__global__ void __launch_bounds__(512, 1)
proj_kernel(const float* __restrict__ x, const float* __restrict__ W1) {
    extern __shared__ float psm[];
    float* xs = psm + P_XS;
    float* ws = psm + P_WS;

    int b  = blockIdx.x >> 4;
    int r0 = (blockIdx.x & 15) << 4;
    int t  = threadIdx.x;

    {
        float4* xs4 = (float4*)xs;
        const float4* xg = (const float4*)(x + (b * LL + r0) * DD);
        #pragma unroll
        for (int u = t; u < 16 * DD / 4; u += 512) {
            int row = u >> 6;
            int c4  = u & 63;
            xs4[row * (XPAD / 4) + c4] = xg[u];
        }
    }

    int k = t >> 4;
    int r = t & 15;

    #pragma unroll
    for (int kc = 0; kc < KK; kc += 32) {
        __syncthreads();
        float4* ws4 = (float4*)ws;
        const float4* wg = (const float4*)(W1 + kc * 2 * DD);
        #pragma unroll
        for (int u = t; u < 32 * 2 * DD / 4; u += 512) ws4[u] = wg[u];
        __syncthreads();

        const ulonglong2* xa = (const ulonglong2*)(xs + r * XPAD);
        const ulonglong2* wi = (const ulonglong2*)(ws + k * 2 * DD);
        const ulonglong2* wj = (const ulonglong2*)(ws + k * 2 * DD + DD);

        unsigned long long aq0 = 0ull, aq1 = 0ull, ak0 = 0ull, ak1 = 0ull;
        #pragma unroll 8
        for (int d4 = 0; d4 < DD / 4; d4++) {
            ulonglong2 xv  = xa[d4];
            ulonglong2 wiv = wi[d4];
            ulonglong2 wjv = wj[d4];
            aq0 = fma2u(xv.x, wiv.x, aq0);
            aq1 = fma2u(xv.y, wiv.y, aq1);
            ak0 = fma2u(xv.x, wjv.x, ak0);
            ak1 = fma2u(xv.y, wjv.y, ak1);
        }
        float2 f;
        float qs, ks;
        f = u2f2(aq0); qs  = f.x + f.y;
        f = u2f2(aq1); qs += f.x + f.y;
        f = u2f2(ak0); ks  = f.x + f.y;
        f = u2f2(ak1); ks += f.x + f.y;

        int kk = kc + k;
        int rg = r0 + r;
        g_qi [(b * LL + rg) * KK + kk] = qs * TANH_C;
        g_kjT[(b * KK + kk) * LL + rg] = ks * TANH_C;
    }
}

// ---------------------------------------------------------------------------
// Kernel 2: fused scores + softmax + context + concat
// grid = 512 blocks (8 b x 64 i-tiles of 4), 512 threads, ~26 KB smem, 4 blk/SM.
// Phase A: thread (tj, p) -> i-pair p over j=tj; kj streamed via double-buffered
//          8-k smem chunks. Phase C: thread (tj, p) -> j-half p, all 4 i's.
// ---------------------------------------------------------------------------
#define CHUNK 8
#define NCHUNK (KK / CHUNK)   // 8

__global__ void __launch_bounds__(512, 4)
attn_kernel(const float* __restrict__ x, const float* __restrict__ W2,
            float* __restrict__ out) {
    __shared__ __align__(16) float kjc[2][CHUNK * LL];   // 2 x 8 KB
    __shared__ __align__(16) float qis_t[KK * IPB];      // [k][i] 1 KB
    __shared__ __align__(16) float scoresS[IPB * LL];    // 4 KB (reused as ctx partials)
    __shared__ __align__(16) float attnT[LL * IPB];      // [j][i] 4 KB, 16B rows
    __shared__ __align__(16) unsigned long long w2d[KK]; // pre-doubled, pre-dup'd

    int b  = blockIdx.x >> 6;
    int i0 = (blockIdx.x & 63) * IPB;
    int t  = threadIdx.x;
    int tj = t & 255;
    int p  = t >> 8;

    const float* kjsrc = g_kjT + b * KK * LL;   // k-major, chunks contiguous

    // stage qi tile (transposed), w2 (doubled+dup), chunk 0
    if (t < KK * IPB) {
        int i = t & 3, k = t >> 2;
        qis_t[k * IPB + i] = g_qi[(b * LL + i0 + i) * KK + k];
    }
    if (t < KK) w2d[t] = dupf(2.0f * W2[t]);
    ((float4*)kjc[0])[t] = __ldg((const float4*)kjsrc + t);
    __syncthreads();

    // ---- Phase A: acc(i-pair p) over k, kv from smem chunks ----
    unsigned long long acc = 0ull;
    unsigned long long two2 = dupf(2.0f);
    const float* qt = qis_t + p * 2;

    for (int c = 0; c < NCHUNK; c++) {
        float4 nxt;
        if (c < NCHUNK - 1)
            nxt = __ldg((const float4*)kjsrc + (c + 1) * (CHUNK * LL / 4) + t);

        const float* kb = kjc[c & 1];
        #pragma unroll
        for (int u = 0; u < CHUNK; u++) {
            int kk = c * CHUNK + u;
            float kv = kb[u * LL + tj];
            float2 q = *(const float2*)(qt + kk * IPB);
            sig_acc(q.x, q.y, kv, w2d[kk], two2, acc);
        }

        if (c < NCHUNK - 1) {
            ((float4*)kjc[(c + 1) & 1])[t] = nxt;
            __syncthreads();
        }
    }
    {
        float2 a = u2f2(acc);
        scoresS[(p * 2 + 0) * LL + tj] = a.x;
        scoresS[(p * 2 + 1) * LL + tj] = a.y;
    }
    __syncthreads();

    // ---- Phase B: softmax over j; warps 0-3, one i each ----
    if (t < 128) {
        int w = t >> 5, lane = t & 31;
        float v[8];
        float mx = -1e30f;
        #pragma unroll
        for (int r = 0; r < 8; r++) {
            v[r] = scoresS[w * LL + lane + 32 * r];
            mx = fmaxf(mx, v[r]);
        }
        #pragma unroll
        for (int o = 16; o; o >>= 1) mx = fmaxf(mx, __shfl_xor_sync(0xffffffffu, mx, o));
        float s = 0.f;
        #pragma unroll
        for (int r = 0; r < 8; r++) { v[r] = __expf(v[r] - mx); s += v[r]; }
        #pragma unroll
        for (int o = 16; o; o >>= 1) s += __shfl_xor_sync(0xffffffffu, s, o);
        float inv = 1.f / s;
        #pragma unroll
        for (int r = 0; r < 8; r++)
            attnT[(lane + 32 * r) * IPB + w] = v[r] * inv;
    }
    __syncthreads();

    // ---- Phase C: thread (tj,p) accumulates ctx for ALL 4 i over j-half p ----
    unsigned long long a0 = 0ull, a1 = 0ull;
    const float* xb = x + b * LL * DD;
    const float* xc = xb + tj;
    {
        int jb = p * 128;
        #pragma unroll 8
        for (int j = 0; j < 128; j++) {
            int jj = jb + j;
            float xv = __ldg(xc + jj * DD);
            ulonglong2 at = *(const ulonglong2*)(attnT + jj * IPB);  // 4 i's, bcast
            unsigned long long xx = dupf(xv);
            a0 = fma2u(at.x, xx, a0);
            a1 = fma2u(at.y, xx, a1);
        }
    }
    // combine halves via smem (reuse scoresS)
    ulonglong2* ctxp = (ulonglong2*)scoresS;   // [tj] -> 16B
    if (p == 1) {
        ulonglong2 v; v.x = a0; v.y = a1;
        ctxp[tj] = v;
    }
    __syncthreads();

    if (p == 0) {
        ulonglong2 o = ctxp[tj];
        a0 = add2u(a0, o.x);
        a1 = add2u(a1, o.y);
        float2 c0 = u2f2(a0), c1 = u2f2(a1);
        float cs[4] = {c0.x, c0.y, c1.x, c1.y};
        #pragma unroll
        for (int r = 0; r < 4; r++)
            out[(unsigned)(b * LL + i0 + r) * (2 * DD) + DD + tj] = cs[r];
    } else {
        #pragma unroll
        for (int r = 0; r < 4; r++)
            out[(unsigned)(b * LL + i0 + r) * (2 * DD) + tj] =
                __ldg(xb + (i0 + r) * DD + tj);
    }
}

// ---------------------------------------------------------------------------
extern "C" void kernel_launch(void* const* d_in, const int* in_sizes, int n_in,
                              void* d_out, int out_size) {
    const float* x  = (const float*)d_in[0];   // (8,256,256)
    const float* W1 = (const float*)d_in[1];   // (64,512)
    const float* W2 = (const float*)d_in[2];   // (1,64)
    float* out = (float*)d_out;                // (8,256,512)

    cudaFuncSetAttribute(proj_kernel,
                         cudaFuncAttributeMaxDynamicSharedMemorySize,
                         PROJ_SMEM_BYTES);
    proj_kernel<<<BB * (LL / 16), 512, PROJ_SMEM_BYTES>>>(x, W1);

    attn_kernel<<<BB * (LL / IPB), 512>>>(x, W2, out);
}

// round 13
// speedup vs baseline: 1.3449x; 1.2963x over previous
#include <cuda_runtime.h>

#define BB 8
#define LL 256
#define DD 256
#define KK 64
#define IPB 16           // i-rows per block (4 per thread-quarter)

#define TANH_C 2.885390081777927f   // 2*log2(e): e^(2x) = exp2(C*x)

// scratch: projections, PRE-SCALED by TANH_C
__device__ float g_qi[BB*LL*KK];    // [b][i][k]
__device__ float g_kjT[BB*KK*LL];   // [b][k][j]

__device__ __forceinline__ unsigned long long fma2u(unsigned long long a,
                                                    unsigned long long b,
                                                    unsigned long long c) {
    unsigned long long d;
    asm("fma.rn.f32x2 %0, %1, %2, %3;" : "=l"(d) : "l"(a), "l"(b), "l"(c));
    return d;
}
__device__ __forceinline__ unsigned long long add2u(unsigned long long a,
                                                    unsigned long long b) {
    unsigned long long d;
    asm("add.rn.f32x2 %0, %1, %2;" : "=l"(d) : "l"(a), "l"(b));
    return d;
}
__device__ __forceinline__ float2 u2f2(unsigned long long v) {
    float2 r;
    asm("mov.b64 {%0, %1}, %2;" : "=f"(r.x), "=f"(r.y) : "l"(v));
    return r;
}
__device__ __forceinline__ unsigned long long dupf(float v) {
    unsigned long long d;
    asm("mov.b64 %0, {%1, %1};" : "=l"(d) : "f"(v));
    return d;
}
__device__ __forceinline__ float fast_ex2(float x) {
    float y; asm("ex2.approx.f32 %0, %1;" : "=f"(y) : "f"(x)); return y;
}
__device__ __forceinline__ float fast_rcp(float x) {
    float y; asm("rcp.approx.f32 %0, %1;" : "=f"(y) : "f"(x)); return y;
}

// ---------------------------------------------------------------------------
// Kernel 1: qi[b,i,k] = C * x[b,i,:]·W1[k,0:256], kjT[b,k,j] = C * x[b,j,:]·W1[k,256:512]
// (unchanged)
// ---------------------------------------------------------------------------
#define XPAD 260
#define P_XS 0
#define P_WS (16 * XPAD)
#define PROJ_SMEM_FLOATS (P_WS + 32 * 2 * DD)
#define PROJ_SMEM_BYTES  (PROJ_SMEM_FLOATS * 4)

__device__ __forceinline__ unsigned long long mul2u(unsigned long long a,
                                                    unsigned long long b) {
    unsigned long long d;
    asm("mul.rn.f32x2 %0, %1, %2;" : "=l"(d) : "l"(a), "l"(b));
    return d;
}

__global__ void __launch_bounds__(512, 1)
proj_kernel(const float* __restrict__ x, const float* __restrict__ W1) {
    extern __shared__ float psm[];
    float* xs = psm + P_XS;
    float* ws = psm + P_WS;

    int b  = blockIdx.x >> 4;
    int r0 = (blockIdx.x & 15) << 4;
    int t  = threadIdx.x;

    {
        float4* xs4 = (float4*)xs;
        const float4* xg = (const float4*)(x + (b * LL + r0) * DD);
        #pragma unroll
        for (int u = t; u < 16 * DD / 4; u += 512) {
            int row = u >> 6;
            int c4  = u & 63;
            xs4[row * (XPAD / 4) + c4] = xg[u];
        }
    }

    int k = t >> 4;
    int r = t & 15;

    #pragma unroll
    for (int kc = 0; kc < KK; kc += 32) {
        __syncthreads();
        float4* ws4 = (float4*)ws;
        const float4* wg = (const float4*)(W1 + kc * 2 * DD);
        #pragma unroll
        for (int u = t; u < 32 * 2 * DD / 4; u += 512) ws4[u] = wg[u];
        __syncthreads();

        const ulonglong2* xa = (const ulonglong2*)(xs + r * XPAD);
        const ulonglong2* wi = (const ulonglong2*)(ws + k * 2 * DD);
        const ulonglong2* wj = (const ulonglong2*)(ws + k * 2 * DD + DD);

        unsigned long long aq0 = 0ull, aq1 = 0ull, ak0 = 0ull, ak1 = 0ull;
        #pragma unroll 8
        for (int d4 = 0; d4 < DD / 4; d4++) {
            ulonglong2 xv  = xa[d4];
            ulonglong2 wiv = wi[d4];
            ulonglong2 wjv = wj[d4];
            aq0 = fma2u(xv.x, wiv.x, aq0);
            aq1 = fma2u(xv.y, wiv.y, aq1);
            ak0 = fma2u(xv.x, wjv.x, ak0);
            ak1 = fma2u(xv.y, wjv.y, ak1);
        }
        float2 f;
        float qs, ks;
        f = u2f2(aq0); qs  = f.x + f.y;
        f = u2f2(aq1); qs += f.x + f.y;
        f = u2f2(ak0); ks  = f.x + f.y;
        f = u2f2(ak1); ks += f.x + f.y;

        int kk = kc + k;
        int rg = r0 + r;
        g_qi [(b * LL + rg) * KK + kk] = qs * TANH_C;
        g_kjT[(b * KK + kk) * LL + rg] = ks * TANH_C;
    }
}

// ---------------------------------------------------------------------------
// Kernel 2: fused scores + softmax + context + concat
// grid = 128 blocks (8 b x 16 i-tiles of 16), 1024 threads, ~100 KB dyn smem.
// Thread (tj = t&255, quarter = t>>8):
//   Phase A: 4 i's (quarter*4..+4) over j=tj; kv from one-shot smem slab;
//            4-wide batched reciprocal (1 rcp serves 4 sigmoids).
//   Phase C: ALL 16 i's (8 packed pairs) over j-quarter [q*64, q*64+64);
//            partials combined once through smem (reusing the kjs slab).
// ---------------------------------------------------------------------------
#define A_KJ   0                         // [k][j] 64x256 = 64 KB (reused as red)
#define A_SC   (KK*LL)                   // scores [i][j] 16x256 = 16 KB
#define A_AT   (A_SC + IPB*LL)           // attnT  [j][i] 256x16 = 16 KB
#define A_QT   (A_AT + LL*IPB)           // qis_t  [k][i] 64x16  =  4 KB
#define A_W2   (A_QT + KK*IPB)           // 2*W2
#define ATT_SMEM_FLOATS (A_W2 + KK)
#define ATT_SMEM_BYTES  (ATT_SMEM_FLOATS * 4)

__global__ void __launch_bounds__(1024, 1)
attn_kernel(const float* __restrict__ x, const float* __restrict__ W2,
            float* __restrict__ out) {
    extern __shared__ float asm_[];
    float* kjs     = asm_ + A_KJ;
    float* scoresS = asm_ + A_SC;
    float* attnT   = asm_ + A_AT;
    float* qis_t   = asm_ + A_QT;
    float* w2s     = asm_ + A_W2;

    int b  = blockIdx.x >> 4;
    int i0 = (blockIdx.x & 15) * IPB;
    int t  = threadIdx.x;
    int tj = t & 255;
    int q  = t >> 8;     // quarter

    // ---- one-shot stage: kjT[b] slab (64 KB), qi tile transposed, 2*W2 ----
    {
        float4* kjs4 = (float4*)kjs;
        const float4* kg = (const float4*)(g_kjT + b * KK * LL);
        #pragma unroll
        for (int u = t; u < KK * LL / 4; u += 1024) kjs4[u] = __ldg(kg + u);
        {
            int i = t & 15, k = t >> 4;   // t<1024 covers 64x16
            qis_t[k * IPB + i] = g_qi[(b * LL + i0 + i) * KK + k];
        }
        if (t < KK) w2s[t] = 2.0f * W2[t];
    }
    __syncthreads();

    // ---- Phase A: 4 i's per thread; batched reciprocal (1 rcp / 4 elems) ----
    float acc0 = 0.f, acc1 = 0.f, acc2 = 0.f, acc3 = 0.f;
    const float* qt = qis_t + q * 4;

    #pragma unroll 4
    for (int k = 0; k < KK; k++) {
        float kv = kjs[k * LL + tj];
        float w  = w2s[k];
        float4 qv = *(const float4*)(qt + k * IPB);
        float e0 = fast_ex2(qv.x + kv);
        float e1 = fast_ex2(qv.y + kv);
        float e2 = fast_ex2(qv.z + kv);
        float e3 = fast_ex2(qv.w + kv);
        float d0 = e0 + 1.0f, d1 = e1 + 1.0f;
        float d2 = e2 + 1.0f, d3 = e3 + 1.0f;
        float p1 = d0 * d1;
        float p2 = p1 * d2;
        float p3 = p2 * d3;
        float r  = fast_rcp(p3);         // 1/(d0 d1 d2 d3)
        float y3 = r * p2;               // 1/d3
        float r2 = r * d3;               // 1/(d0 d1 d2)
        float y2 = r2 * p1;              // 1/d2
        float r3 = r2 * d2;              // 1/(d0 d1)
        float y0 = r3 * d1;              // 1/d0
        float y1 = r3 * d0;              // 1/d1
        acc0 = fmaf(w, y0, acc0);
        acc1 = fmaf(w, y1, acc1);
        acc2 = fmaf(w, y2, acc2);
        acc3 = fmaf(w, y3, acc3);
    }
    // score' = -2*sum(w/d) with the 2 folded into w2s; const term dropped
    scoresS[(q * 4 + 0) * LL + tj] = -acc0;
    scoresS[(q * 4 + 1) * LL + tj] = -acc1;
    scoresS[(q * 4 + 2) * LL + tj] = -acc2;
    scoresS[(q * 4 + 3) * LL + tj] = -acc3;
    __syncthreads();

    // ---- Phase B: softmax over j; warps 0-15 handle one i each ----
    if (t < 512) {
        int w = t >> 5, lane = t & 31;
        float v[8];
        float mx = -1e30f;
        #pragma unroll
        for (int r = 0; r < 8; r++) {
            v[r] = scoresS[w * LL + lane + 32 * r];
            mx = fmaxf(mx, v[r]);
        }
        #pragma unroll
        for (int o = 16; o; o >>= 1) mx = fmaxf(mx, __shfl_xor_sync(0xffffffffu, mx, o));
        float s = 0.f;
        #pragma unroll
        for (int r = 0; r < 8; r++) { v[r] = __expf(v[r] - mx); s += v[r]; }
        #pragma unroll
        for (int o = 16; o; o >>= 1) s += __shfl_xor_sync(0xffffffffu, s, o);
        float inv = 1.f / s;
        #pragma unroll
        for (int r = 0; r < 8; r++)
            attnT[(lane + 32 * r) * IPB + w] = v[r] * inv;
    }
    __syncthreads();

    // ---- Phase C: all 16 i's (8 packed pairs) over this quarter's 64 j ----
    unsigned long long a[8];
    #pragma unroll
    for (int p = 0; p < 8; p++) a[p] = 0ull;

    const float* xb = x + b * LL * DD;
    {
        const float* xc = xb + tj;
        int jb = q * 64;
        #pragma unroll 8
        for (int j = 0; j < 64; j++) {
            int jj = jb + j;
            float xv = __ldg(xc + jj * DD);
            unsigned long long xx = dupf(xv);
            const ulonglong2* atp = (const ulonglong2*)(attnT + jj * IPB);
            ulonglong2 q0 = atp[0], q1 = atp[1];
            a[0] = fma2u(q0.x, xx, a[0]);
            a[1] = fma2u(q0.y, xx, a[1]);
            a[2] = fma2u(q1.x, xx, a[2]);
            a[3] = fma2u(q1.y, xx, a[3]);
            ulonglong2 q2 = atp[2], q3 = atp[3];
            a[4] = fma2u(q2.x, xx, a[4]);
            a[5] = fma2u(q2.y, xx, a[5]);
            a[6] = fma2u(q3.x, xx, a[6]);
            a[7] = fma2u(q3.y, xx, a[7]);
        }
    }

    // partials -> smem (reuse kjs slab: 32 rows x 256 ull = 64 KB)
    unsigned long long* red = (unsigned long long*)kjs;
    #pragma unroll
    for (int p = 0; p < 8; p++) red[(q * 8 + p) * LL + tj] = a[p];
    __syncthreads();

    // quarter q reduces pairs {2q, 2q+1} and writes ctx; also copies 4 x-rows
    #pragma unroll
    for (int pp = 0; pp < 2; pp++) {
        int p = q * 2 + pp;
        unsigned long long s = red[p * LL + tj];
        s = add2u(s, red[(8 + p) * LL + tj]);
        s = add2u(s, red[(16 + p) * LL + tj]);
        s = add2u(s, red[(24 + p) * LL + tj]);
        float2 c = u2f2(s);
        out[(unsigned)(b * LL + i0 + 2 * p) * (2 * DD) + DD + tj]     = c.x;
        out[(unsigned)(b * LL + i0 + 2 * p + 1) * (2 * DD) + DD + tj] = c.y;
    }
    #pragma unroll
    for (int r = 0; r < 4; r++) {
        int i = q * 4 + r;
        out[(unsigned)(b * LL + i0 + i) * (2 * DD) + tj] =
            __ldg(xb + (i0 + i) * DD + tj);
    }
}

// ---------------------------------------------------------------------------
extern "C" void kernel_launch(void* const* d_in, const int* in_sizes, int n_in,
                              void* d_out, int out_size) {
    const float* x  = (const float*)d_in[0];   // (8,256,256)
    const float* W1 = (const float*)d_in[1];   // (64,512)
    const float* W2 = (const float*)d_in[2];   // (1,64)
    float* out = (float*)d_out;                // (8,256,512)

    cudaFuncSetAttribute(proj_kernel,
                         cudaFuncAttributeMaxDynamicSharedMemorySize,
                         PROJ_SMEM_BYTES);
    proj_kernel<<<BB * (LL / 16), 512, PROJ_SMEM_BYTES>>>(x, W1);

    cudaFuncSetAttribute(attn_kernel,
                         cudaFuncAttributeMaxDynamicSharedMemorySize,
                         ATT_SMEM_BYTES);
    attn_kernel<<<BB * (LL / IPB), 1024, ATT_SMEM_BYTES>>>(x, W2, out);
}

// round 14
// speedup vs baseline: 1.5013x; 1.1163x over previous
#include <cuda_runtime.h>

#define BB 8
#define LL 256
#define DD 256
#define KK 64
#define IPB 16           // i-rows per block (4 per thread-quarter)

#define TANH_C 2.885390081777927f   // 2*log2(e): e^(2x) = exp2(C*x)
#define LOG2E  1.4426950408889634f

// scratch: EXPONENTIATED projections: E = exp2(C * proj)
__device__ float g_qi[BB*LL*KK];    // [b][i][k]  = exp2(C*qi)
__device__ float g_kjT[BB*KK*LL];   // [b][k][j]  = exp2(C*kj)

__device__ __forceinline__ unsigned long long fma2u(unsigned long long a,
                                                    unsigned long long b,
                                                    unsigned long long c) {
    unsigned long long d;
    asm("fma.rn.f32x2 %0, %1, %2, %3;" : "=l"(d) : "l"(a), "l"(b), "l"(c));
    return d;
}
__device__ __forceinline__ unsigned long long add2u(unsigned long long a,
                                                    unsigned long long b) {
    unsigned long long d;
    asm("add.rn.f32x2 %0, %1, %2;" : "=l"(d) : "l"(a), "l"(b));
    return d;
}
__device__ __forceinline__ float2 u2f2(unsigned long long v) {
    float2 r;
    asm("mov.b64 {%0, %1}, %2;" : "=f"(r.x), "=f"(r.y) : "l"(v));
    return r;
}
__device__ __forceinline__ unsigned long long dupf(float v) {
    unsigned long long d;
    asm("mov.b64 %0, {%1, %1};" : "=l"(d) : "f"(v));
    return d;
}
__device__ __forceinline__ float fast_ex2(float x) {
    float y; asm("ex2.approx.f32 %0, %1;" : "=f"(y) : "f"(x)); return y;
}
__device__ __forceinline__ float fast_rcp(float x) {
    float y; asm("rcp.approx.f32 %0, %1;" : "=f"(y) : "f"(x)); return y;
}

// ---------------------------------------------------------------------------
// Kernel 1: E_q[b,i,k] = exp2(C * x[b,i,:]·W1i[k]), E_k[b,k,j] = exp2(C * x[b,j,:]·W1j[k])
// ---------------------------------------------------------------------------
#define XPAD 260
#define P_XS 0
#define P_WS (16 * XPAD)
#define PROJ_SMEM_FLOATS (P_WS + 32 * 2 * DD)
#define PROJ_SMEM_BYTES  (PROJ_SMEM_FLOATS * 4)

__global__ void __launch_bounds__(512, 1)
proj_kernel(const float* __restrict__ x, const float* __restrict__ W1) {
    extern __shared__ float psm[];
    float* xs = psm + P_XS;
    float* ws = psm + P_WS;

    int b  = blockIdx.x >> 4;
    int r0 = (blockIdx.x & 15) << 4;
    int t  = threadIdx.x;

    {
        float4* xs4 = (float4*)xs;
        const float4* xg = (const float4*)(x + (b * LL + r0) * DD);
        #pragma unroll
        for (int u = t; u < 16 * DD / 4; u += 512) {
            int row = u >> 6;
            int c4  = u & 63;
            xs4[row * (XPAD / 4) + c4] = xg[u];
        }
    }

    int k = t >> 4;
    int r = t & 15;

    #pragma unroll
    for (int kc = 0; kc < KK; kc += 32) {
        __syncthreads();
        float4* ws4 = (float4*)ws;
        const float4* wg = (const float4*)(W1 + kc * 2 * DD);
        #pragma unroll
        for (int u = t; u < 32 * 2 * DD / 4; u += 512) ws4[u] = wg[u];
        __syncthreads();

        const ulonglong2* xa = (const ulonglong2*)(xs + r * XPAD);
        const ulonglong2* wi = (const ulonglong2*)(ws + k * 2 * DD);
        const ulonglong2* wj = (const ulonglong2*)(ws + k * 2 * DD + DD);

        unsigned long long aq0 = 0ull, aq1 = 0ull, ak0 = 0ull, ak1 = 0ull;
        #pragma unroll 8
        for (int d4 = 0; d4 < DD / 4; d4++) {
            ulonglong2 xv  = xa[d4];
            ulonglong2 wiv = wi[d4];
            ulonglong2 wjv = wj[d4];
            aq0 = fma2u(xv.x, wiv.x, aq0);
            aq1 = fma2u(xv.y, wiv.y, aq1);
            ak0 = fma2u(xv.x, wjv.x, ak0);
            ak1 = fma2u(xv.y, wjv.y, ak1);
        }
        float2 f;
        float qs, ks;
        f = u2f2(aq0); qs  = f.x + f.y;
        f = u2f2(aq1); qs += f.x + f.y;
        f = u2f2(ak0); ks  = f.x + f.y;
        f = u2f2(ak1); ks += f.x + f.y;

        int kk = kc + k;
        int rg = r0 + r;
        g_qi [(b * LL + rg) * KK + kk] = fast_ex2(qs * TANH_C);
        g_kjT[(b * KK + kk) * LL + rg] = fast_ex2(ks * TANH_C);
    }
}

// ---------------------------------------------------------------------------
// Kernel 2: fused scores + softmax + context + concat
// grid = 128 blocks (8 b x 16 i-tiles of 16), 1024 threads, ~100 KB dyn smem.
// Phase A: d = fma(Eq, Ek, 1) -- NO ex2 in loop; 1 rcp per 4 elements.
// scores pre-scaled by log2e (folded into staged w2) so phase B uses bare ex2.
// ---------------------------------------------------------------------------
#define A_KJ   0                         // E_k [k][j] 64x256 = 64 KB (reused as red)
#define A_SC   (KK*LL)                   // scores [i][j] 16x256 = 16 KB
#define A_AT   (A_SC + IPB*LL)           // attnT  [j][i] 256x16 = 16 KB
#define A_QT   (A_AT + LL*IPB)           // E_q^T  [k][i] 64x16  =  4 KB
#define A_W2   (A_QT + KK*IPB)           // 2*log2e*W2
#define ATT_SMEM_FLOATS (A_W2 + KK)
#define ATT_SMEM_BYTES  (ATT_SMEM_FLOATS * 4)

__global__ void __launch_bounds__(1024, 1)
attn_kernel(const float* __restrict__ x, const float* __restrict__ W2,
            float* __restrict__ out) {
    extern __shared__ float asm_[];
    float* kjs     = asm_ + A_KJ;
    float* scoresS = asm_ + A_SC;
    float* attnT   = asm_ + A_AT;
    float* qis_t   = asm_ + A_QT;
    float* w2s     = asm_ + A_W2;

    int b  = blockIdx.x >> 4;
    int i0 = (blockIdx.x & 15) * IPB;
    int t  = threadIdx.x;
    int tj = t & 255;
    int q  = t >> 8;     // quarter

    // ---- one-shot stage: E_k slab (64 KB), E_q tile transposed, scaled W2 ----
    {
        float4* kjs4 = (float4*)kjs;
        const float4* kg = (const float4*)(g_kjT + b * KK * LL);
        #pragma unroll
        for (int u = t; u < KK * LL / 4; u += 1024) kjs4[u] = __ldg(kg + u);
        {
            int i = t & 15, k = t >> 4;   // t<1024 covers 64x16
            qis_t[k * IPB + i] = g_qi[(b * LL + i0 + i) * KK + k];
        }
        if (t < KK) w2s[t] = (2.0f * LOG2E) * W2[t];
    }
    __syncthreads();

    // ---- Phase A: 4 i's per thread; d = fma(Eq,Ek,1); 1 rcp / 4 elems ----
    float acc0 = 0.f, acc1 = 0.f, acc2 = 0.f, acc3 = 0.f;
    const float* qt = qis_t + q * 4;

    #pragma unroll 4
    for (int k = 0; k < KK; k++) {
        float ek = kjs[k * LL + tj];
        float w  = w2s[k];
        float4 eq = *(const float4*)(qt + k * IPB);
        float d0 = fmaf(eq.x, ek, 1.0f);
        float d1 = fmaf(eq.y, ek, 1.0f);
        float d2 = fmaf(eq.z, ek, 1.0f);
        float d3 = fmaf(eq.w, ek, 1.0f);
        float p1 = d0 * d1;
        float p2 = p1 * d2;
        float p3 = p2 * d3;
        float r  = fast_rcp(p3);         // 1/(d0 d1 d2 d3)
        float y3 = r * p2;               // 1/d3
        float r2 = r * d3;               // 1/(d0 d1 d2)
        float y2 = r2 * p1;              // 1/d2
        float r3 = r2 * d2;              // 1/(d0 d1)
        float y0 = r3 * d1;              // 1/d0
        float y1 = r3 * d0;              // 1/d1
        acc0 = fmaf(w, y0, acc0);
        acc1 = fmaf(w, y1, acc1);
        acc2 = fmaf(w, y2, acc2);
        acc3 = fmaf(w, y3, acc3);
    }
    // score'' = -log2e*2*sum(w/d); const term dropped (softmax-invariant)
    scoresS[(q * 4 + 0) * LL + tj] = -acc0;
    scoresS[(q * 4 + 1) * LL + tj] = -acc1;
    scoresS[(q * 4 + 2) * LL + tj] = -acc2;
    scoresS[(q * 4 + 3) * LL + tj] = -acc3;
    __syncthreads();

    // ---- Phase B: softmax over j (scores in log2 domain -> bare ex2) ----
    if (t < 512) {
        int w = t >> 5, lane = t & 31;
        float v[8];
        float mx = -1e30f;
        #pragma unroll
        for (int r = 0; r < 8; r++) {
            v[r] = scoresS[w * LL + lane + 32 * r];
            mx = fmaxf(mx, v[r]);
        }
        #pragma unroll
        for (int o = 16; o; o >>= 1) mx = fmaxf(mx, __shfl_xor_sync(0xffffffffu, mx, o));
        float s = 0.f;
        #pragma unroll
        for (int r = 0; r < 8; r++) { v[r] = fast_ex2(v[r] - mx); s += v[r]; }
        #pragma unroll
        for (int o = 16; o; o >>= 1) s += __shfl_xor_sync(0xffffffffu, s, o);
        float inv = 1.f / s;
        #pragma unroll
        for (int r = 0; r < 8; r++)
            attnT[(lane + 32 * r) * IPB + w] = v[r] * inv;
    }
    __syncthreads();

    // ---- Phase C: all 16 i's (8 packed pairs) over this quarter's 64 j ----
    unsigned long long a[8];
    #pragma unroll
    for (int p = 0; p < 8; p++) a[p] = 0ull;

    const float* xb = x + b * LL * DD;
    {
        const float* xc = xb + tj;
        int jb = q * 64;
        #pragma unroll 8
        for (int j = 0; j < 64; j++) {
            int jj = jb + j;
            float xv = __ldg(xc + jj * DD);
            unsigned long long xx = dupf(xv);
            const ulonglong2* atp = (const ulonglong2*)(attnT + jj * IPB);
            ulonglong2 q0 = atp[0], q1 = atp[1];
            a[0] = fma2u(q0.x, xx, a[0]);
            a[1] = fma2u(q0.y, xx, a[1]);
            a[2] = fma2u(q1.x, xx, a[2]);
            a[3] = fma2u(q1.y, xx, a[3]);
            ulonglong2 q2 = atp[2], q3 = atp[3];
            a[4] = fma2u(q2.x, xx, a[4]);
            a[5] = fma2u(q2.y, xx, a[5]);
            a[6] = fma2u(q3.x, xx, a[6]);
            a[7] = fma2u(q3.y, xx, a[7]);
        }
    }

    // partials -> smem (reuse kjs slab: 32 rows x 256 ull = 64 KB)
    unsigned long long* red = (unsigned long long*)kjs;
    #pragma unroll
    for (int p = 0; p < 8; p++) red[(q * 8 + p) * LL + tj] = a[p];
    __syncthreads();

    // quarter q reduces pairs {2q, 2q+1} and writes ctx; also copies 4 x-rows
    #pragma unroll
    for (int pp = 0; pp < 2; pp++) {
        int p = q * 2 + pp;
        unsigned long long s = red[p * LL + tj];
        s = add2u(s, red[(8 + p) * LL + tj]);
        s = add2u(s, red[(16 + p) * LL + tj]);
        s = add2u(s, red[(24 + p) * LL + tj]);
        float2 c = u2f2(s);
        out[(unsigned)(b * LL + i0 + 2 * p) * (2 * DD) + DD + tj]     = c.x;
        out[(unsigned)(b * LL + i0 + 2 * p + 1) * (2 * DD) + DD + tj] = c.y;
    }
    #pragma unroll
    for (int r = 0; r < 4; r++) {
        int i = q * 4 + r;
        out[(unsigned)(b * LL + i0 + i) * (2 * DD) + tj] =
            __ldg(xb + (i0 + i) * DD + tj);
    }
}

// ---------------------------------------------------------------------------
extern "C" void kernel_launch(void* const* d_in, const int* in_sizes, int n_in,
                              void* d_out, int out_size) {
    const float* x  = (const float*)d_in[0];   // (8,256,256)
    const float* W1 = (const float*)d_in[1];   // (64,512)
    const float* W2 = (const float*)d_in[2];   // (1,64)
    float* out = (float*)d_out;                // (8,256,512)

    cudaFuncSetAttribute(proj_kernel,
                         cudaFuncAttributeMaxDynamicSharedMemorySize,
                         PROJ_SMEM_BYTES);
    proj_kernel<<<BB * (LL / 16), 512, PROJ_SMEM_BYTES>>>(x, W1);

    cudaFuncSetAttribute(attn_kernel,
                         cudaFuncAttributeMaxDynamicSharedMemorySize,
                         ATT_SMEM_BYTES);
    attn_kernel<<<BB * (LL / IPB), 1024, ATT_SMEM_BYTES>>>(x, W2, out);
}

// round 15
// speedup vs baseline: 1.5674x; 1.0441x over previous
#include <cuda_runtime.h>

#define BB 8
#define LL 256
#define DD 256
#define KK 64
#define IPB 16           // i-rows per block (4 per thread-quarter)

#define TANH_C 2.885390081777927f   // 2*log2(e)
#define LOG2E  1.4426950408889634f

// scratch: EXPONENTIATED projections, both [b][row][k] (j-major for E_k!)
__device__ float g_qiE[BB*LL*KK];   // [b][i][k] = exp2(C*qi)
__device__ float g_kjE[BB*LL*KK];   // [b][j][k] = exp2(C*kj)

__device__ __forceinline__ unsigned long long fma2u(unsigned long long a,
                                                    unsigned long long b,
                                                    unsigned long long c) {
    unsigned long long d;
    asm("fma.rn.f32x2 %0, %1, %2, %3;" : "=l"(d) : "l"(a), "l"(b), "l"(c));
    return d;
}
__device__ __forceinline__ unsigned long long add2u(unsigned long long a,
                                                    unsigned long long b) {
    unsigned long long d;
    asm("add.rn.f32x2 %0, %1, %2;" : "=l"(d) : "l"(a), "l"(b));
    return d;
}
__device__ __forceinline__ float2 u2f2(unsigned long long v) {
    float2 r;
    asm("mov.b64 {%0, %1}, %2;" : "=f"(r.x), "=f"(r.y) : "l"(v));
    return r;
}
__device__ __forceinline__ unsigned long long dupf(float v) {
    unsigned long long d;
    asm("mov.b64 %0, {%1, %1};" : "=l"(d) : "f"(v));
    return d;
}
__device__ __forceinline__ unsigned long long packf(float a, float b) {
    unsigned long long d;
    asm("mov.b64 %0, {%1, %2};" : "=l"(d) : "f"(a), "f"(b));
    return d;
}
__device__ __forceinline__ float fast_ex2(float x) {
    float y; asm("ex2.approx.f32 %0, %1;" : "=f"(y) : "f"(x)); return y;
}
__device__ __forceinline__ float fast_rcp(float x) {
    float y; asm("rcp.approx.f32 %0, %1;" : "=f"(y) : "f"(x)); return y;
}

// ---------------------------------------------------------------------------
// Kernel 1: E_q[b,i,k], E_k[b,j,k] (both row-major in k).
// grid = 128 blocks, 1024 threads, ~144 KB smem: ALL 64 W1 rows staged once.
// Thread: k = t>>4 (0..63), r = t&15.
// ---------------------------------------------------------------------------
#define XPAD 260
#define P_XS 0
#define P_WS (16 * XPAD)
#define PROJ_SMEM_FLOATS (P_WS + KK * 2 * DD)
#define PROJ_SMEM_BYTES  (PROJ_SMEM_FLOATS * 4)   // 147712 B

__global__ void __launch_bounds__(1024, 1)
proj_kernel(const float* __restrict__ x, const float* __restrict__ W1) {
    extern __shared__ float psm[];
    float* xs = psm + P_XS;
    float* ws = psm + P_WS;

    int b  = blockIdx.x >> 4;
    int r0 = (blockIdx.x & 15) << 4;
    int t  = threadIdx.x;

    // stage x tile (padded rows): 1024 float4, one each
    {
        float4* xs4 = (float4*)xs;
        const float4* xg = (const float4*)(x + (b * LL + r0) * DD);
        int row = t >> 6, c4 = t & 63;
        xs4[row * (XPAD / 4) + c4] = xg[t];
    }
    // stage ALL of W1: 8192 float4, 8 each (coalesced)
    {
        float4* ws4 = (float4*)ws;
        const float4* wg = (const float4*)W1;
        #pragma unroll
        for (int u = t; u < KK * 2 * DD / 4; u += 1024) ws4[u] = wg[u];
    }
    __syncthreads();

    int k = t >> 4;
    int r = t & 15;

    const ulonglong2* xa = (const ulonglong2*)(xs + r * XPAD);
    const ulonglong2* wi = (const ulonglong2*)(ws + k * 2 * DD);
    const ulonglong2* wj = (const ulonglong2*)(ws + k * 2 * DD + DD);

    unsigned long long aq0 = 0ull, aq1 = 0ull, ak0 = 0ull, ak1 = 0ull;
    #pragma unroll 8
    for (int d4 = 0; d4 < DD / 4; d4++) {
        ulonglong2 xv  = xa[d4];
        ulonglong2 wiv = wi[d4];
        ulonglong2 wjv = wj[d4];
        aq0 = fma2u(xv.x, wiv.x, aq0);
        aq1 = fma2u(xv.y, wiv.y, aq1);
        ak0 = fma2u(xv.x, wjv.x, ak0);
        ak1 = fma2u(xv.y, wjv.y, ak1);
    }
    float2 f;
    float qs, ks;
    f = u2f2(aq0); qs  = f.x + f.y;
    f = u2f2(aq1); qs += f.x + f.y;
    f = u2f2(ak0); ks  = f.x + f.y;
    f = u2f2(ak1); ks += f.x + f.y;

    int rg = r0 + r;
    g_qiE[(b * LL + rg) * KK + k] = fast_ex2(qs * TANH_C);
    g_kjE[(b * LL + rg) * KK + k] = fast_ex2(ks * TANH_C);
}

// ---------------------------------------------------------------------------
// Kernel 2: fused scores + softmax + context + concat
// grid = 128 blocks (8 b x 16 i-tiles of 16), 1024 threads, ~104 KB dyn smem.
// E_k slab [j][k] padded to 68 floats/row -> ek via LDS.128 (4 k at once).
// Phase A: d = fma2(Eq01, ekdup, 1); 1 rcp / 4 elems; w folded into recovery.
// ---------------------------------------------------------------------------
#define KROW 68                          // padded slab row (floats), 272B (16B-aligned)
#define A_KJ   0                         // E_k slab [j][KROW] = 69632 floats (reused as red)
#define A_SC   (LL*KROW)                 // scores [i][j] 16x256
#define A_AT   (A_SC + IPB*LL)           // attnT  [j][i] 256x16
#define A_QT   (A_AT + LL*IPB)           // E_q^T  [k][i] 64x16
#define A_W2   (A_QT + KK*IPB)           // scaled W2
#define ATT_SMEM_FLOATS (A_W2 + KK)
#define ATT_SMEM_BYTES  (ATT_SMEM_FLOATS * 4)

__global__ void __launch_bounds__(1024, 1)
attn_kernel(const float* __restrict__ x, const float* __restrict__ W2,
            float* __restrict__ out) {
    extern __shared__ float asm_[];
    float* kjs     = asm_ + A_KJ;
    float* scoresS = asm_ + A_SC;
    float* attnT   = asm_ + A_AT;
    float* qis_t   = asm_ + A_QT;
    float* w2s     = asm_ + A_W2;

    int b  = blockIdx.x >> 4;
    int i0 = (blockIdx.x & 15) * IPB;
    int t  = threadIdx.x;
    int tj = t & 255;
    int q  = t >> 8;     // quarter

    // ---- stage E_k slab [j][k] (pad 68), E_q^T, scaled W2 ----
    {
        const float4* kg = (const float4*)(g_kjE + b * LL * KK);
        #pragma unroll
        for (int u = t; u < LL * KK / 4; u += 1024) {
            int j = u >> 4, k4 = u & 15;
            *(float4*)(kjs + j * KROW + k4 * 4) = __ldg(kg + u);
        }
        {
            int i = t >> 6, k = t & 63;   // coalesced read of 16 rows
            qis_t[k * IPB + i] = g_qiE[(b * LL + i0 + i) * KK + k];
        }
        if (t < KK) w2s[t] = (2.0f * LOG2E) * W2[t];
    }
    __syncthreads();

    // ---- Phase A: 4 i's per thread; 1 rcp / 4 elems; no ex2 ----
    float acc0 = 0.f, acc1 = 0.f, acc2 = 0.f, acc3 = 0.f;
    const float* qt = qis_t + q * 4;
    const float* ekrow = kjs + tj * KROW;
    unsigned long long one2 = dupf(1.0f);

    #pragma unroll
    for (int kb = 0; kb < KK / 4; kb++) {
        float4 ek4 = *(const float4*)(ekrow + kb * 4);
        #pragma unroll
        for (int u = 0; u < 4; u++) {
            int k = kb * 4 + u;
            float ekv = (u == 0) ? ek4.x : (u == 1) ? ek4.y : (u == 2) ? ek4.z : ek4.w;
            const unsigned long long* eqp =
                (const unsigned long long*)(qt + k * IPB);
            unsigned long long ekd = dupf(ekv);
            unsigned long long d01 = fma2u(eqp[0], ekd, one2);
            unsigned long long d23 = fma2u(eqp[1], ekd, one2);
            float2 D01 = u2f2(d01), D23 = u2f2(d23);
            float p01 = D01.x * D01.y;
            float p23 = D23.x * D23.y;
            float P   = p01 * p23;
            float r   = fast_rcp(P);
            float w   = w2s[k];
            float wr01 = w * (r * p23);   // = w/(d0*d1)
            float wr23 = w * (r * p01);   // = w/(d2*d3)
            acc0 = fmaf(wr01, D01.y, acc0);
            acc1 = fmaf(wr01, D01.x, acc1);
            acc2 = fmaf(wr23, D23.y, acc2);
            acc3 = fmaf(wr23, D23.x, acc3);
        }
    }
    // log2-domain score' = -sum(w'/d); const term dropped (softmax-invariant)
    scoresS[(q * 4 + 0) * LL + tj] = -acc0;
    scoresS[(q * 4 + 1) * LL + tj] = -acc1;
    scoresS[(q * 4 + 2) * LL + tj] = -acc2;
    scoresS[(q * 4 + 3) * LL + tj] = -acc3;
    __syncthreads();

    // ---- Phase B: softmax over j (log2 domain -> bare ex2) ----
    if (t < 512) {
        int w = t >> 5, lane = t & 31;
        float v[8];
        float mx = -1e30f;
        #pragma unroll
        for (int r = 0; r < 8; r++) {
            v[r] = scoresS[w * LL + lane + 32 * r];
            mx = fmaxf(mx, v[r]);
        }
        #pragma unroll
        for (int o = 16; o; o >>= 1) mx = fmaxf(mx, __shfl_xor_sync(0xffffffffu, mx, o));
        float s = 0.f;
        #pragma unroll
        for (int r = 0; r < 8; r++) { v[r] = fast_ex2(v[r] - mx); s += v[r]; }
        #pragma unroll
        for (int o = 16; o; o >>= 1) s += __shfl_xor_sync(0xffffffffu, s, o);
        float inv = 1.f / s;
        #pragma unroll
        for (int r = 0; r < 8; r++)
            attnT[(lane + 32 * r) * IPB + w] = v[r] * inv;
    }
    __syncthreads();

    // ---- Phase C: all 16 i's (8 packed pairs) over this quarter's 64 j ----
    unsigned long long a[8];
    #pragma unroll
    for (int p = 0; p < 8; p++) a[p] = 0ull;

    const float* xb = x + b * LL * DD;
    {
        const float* xc = xb + tj;
        int jb = q * 64;
        #pragma unroll 8
        for (int j = 0; j < 64; j++) {
            int jj = jb + j;
            float xv = __ldg(xc + jj * DD);
            unsigned long long xx = dupf(xv);
            const ulonglong2* atp = (const ulonglong2*)(attnT + jj * IPB);
            ulonglong2 q0 = atp[0], q1 = atp[1];
            a[0] = fma2u(q0.x, xx, a[0]);
            a[1] = fma2u(q0.y, xx, a[1]);
            a[2] = fma2u(q1.x, xx, a[2]);
            a[3] = fma2u(q1.y, xx, a[3]);
            ulonglong2 q2 = atp[2], q3 = atp[3];
            a[4] = fma2u(q2.x, xx, a[4]);
            a[5] = fma2u(q2.y, xx, a[5]);
            a[6] = fma2u(q3.x, xx, a[6]);
            a[7] = fma2u(q3.y, xx, a[7]);
        }
    }

    // partials -> smem (reuse slab: 32 rows x 256 ull = 64 KB <= 69.6 KB)
    unsigned long long* red = (unsigned long long*)kjs;
    #pragma unroll
    for (int p = 0; p < 8; p++) red[(q * 8 + p) * LL + tj] = a[p];
    __syncthreads();

    // quarter q reduces pairs {2q, 2q+1} and writes ctx; also copies 4 x-rows
    #pragma unroll
    for (int pp = 0; pp < 2; pp++) {
        int p = q * 2 + pp;
        unsigned long long s = red[p * LL + tj];
        s = add2u(s, red[(8 + p) * LL + tj]);
        s = add2u(s, red[(16 + p) * LL + tj]);
        s = add2u(s, red[(24 + p) * LL + tj]);
        float2 c = u2f2(s);
        out[(unsigned)(b * LL + i0 + 2 * p) * (2 * DD) + DD + tj]     = c.x;
        out[(unsigned)(b * LL + i0 + 2 * p + 1) * (2 * DD) + DD + tj] = c.y;
    }
    #pragma unroll
    for (int r = 0; r < 4; r++) {
        int i = q * 4 + r;
        out[(unsigned)(b * LL + i0 + i) * (2 * DD) + tj] =
            __ldg(xb + (i0 + i) * DD + tj);
    }
}

// ---------------------------------------------------------------------------
extern "C" void kernel_launch(void* const* d_in, const int* in_sizes, int n_in,
                              void* d_out, int out_size) {
    const float* x  = (const float*)d_in[0];   // (8,256,256)
    const float* W1 = (const float*)d_in[1];   // (64,512)
    const float* W2 = (const float*)d_in[2];   // (1,64)
    float* out = (float*)d_out;                // (8,256,512)

    cudaFuncSetAttribute(proj_kernel,
                         cudaFuncAttributeMaxDynamicSharedMemorySize,
                         PROJ_SMEM_BYTES);
    proj_kernel<<<BB * (LL / 16), 1024, PROJ_SMEM_BYTES>>>(x, W1);

    cudaFuncSetAttribute(attn_kernel,
                         cudaFuncAttributeMaxDynamicSharedMemorySize,
                         ATT_SMEM_BYTES);
    attn_kernel<<<BB * (LL / IPB), 1024, ATT_SMEM_BYTES>>>(x, W2, out);
}

// round 16
// speedup vs baseline: 1.5788x; 1.0072x over previous
#include <cuda_runtime.h>

#define BB 8
#define LL 256
#define DD 256
#define KK 64
#define IPB 16           // i-rows per block (4 per thread-quarter)
#define GRID (BB * (LL / IPB))   // 128

#define TANH_C 2.885390081777927f   // 2*log2(e)
#define LOG2E  1.4426950408889634f

// E_k only goes through global; E_q stays block-local.
__device__ float g_kjE[BB*LL*KK];   // [b][j][k] = exp2(C*kj)
__device__ unsigned g_bar = 0;      // monotonic grid barrier counter

__device__ __forceinline__ unsigned long long fma2u(unsigned long long a,
                                                    unsigned long long b,
                                                    unsigned long long c) {
    unsigned long long d;
    asm("fma.rn.f32x2 %0, %1, %2, %3;" : "=l"(d) : "l"(a), "l"(b), "l"(c));
    return d;
}
__device__ __forceinline__ unsigned long long add2u(unsigned long long a,
                                                    unsigned long long b) {
    unsigned long long d;
    asm("add.rn.f32x2 %0, %1, %2;" : "=l"(d) : "l"(a), "l"(b));
    return d;
}
__device__ __forceinline__ float2 u2f2(unsigned long long v) {
    float2 r;
    asm("mov.b64 {%0, %1}, %2;" : "=f"(r.x), "=f"(r.y) : "l"(v));
    return r;
}
__device__ __forceinline__ unsigned long long dupf(float v) {
    unsigned long long d;
    asm("mov.b64 %0, {%1, %1};" : "=l"(d) : "f"(v));
    return d;
}
__device__ __forceinline__ float fast_ex2(float x) {
    float y; asm("ex2.approx.f32 %0, %1;" : "=f"(y) : "f"(x)); return y;
}
__device__ __forceinline__ float fast_rcp(float x) {
    float y; asm("rcp.approx.f32 %0, %1;" : "=f"(y) : "f"(x)); return y;
}

// ---------------------------------------------------------------------------
// SMEM layout (floats). qis_t/w2s live OUTSIDE the overlapped window so they
// survive from proj phase into attn phase.
//   [F_QT .. )      qis_t  [k][i]   64x16             (written by proj phase)
//   [F_W2 .. )      w2s                               (scaled W2)
//   [F_SH .. )      overlap window:
//        proj: xs [16][XPAD] + ws [64][512]   = 36928 floats
//        attn: slab [j][KROW] + scores + attnT = 25600 floats
// ---------------------------------------------------------------------------
#define XPAD 260
#define KROW 68
#define F_QT 0
#define F_W2 (F_QT + KK*IPB)          // 1024
#define F_SH (F_W2 + KK)              // 1088
#define P_XS F_SH
#define P_WS (F_SH + 16 * XPAD)
#define A_KJ F_SH                     // E_k slab [j][KROW] (reused as red)
#define A_SC (F_SH + LL*KROW)         // scores [i][j] 16x256
#define A_AT (A_SC + IPB*LL)          // attnT  [j][i] 256x16
#define SMEM_FLOATS (P_WS + KK * 2 * DD)   // 1088 + 4160 + 32768 = 38016
#define SMEM_BYTES  (SMEM_FLOATS * 4)      // 152064

__global__ void __launch_bounds__(1024, 1)
fused_kernel(const float* __restrict__ x, const float* __restrict__ W1,
             const float* __restrict__ W2, float* __restrict__ out) {
    extern __shared__ float sm[];
    float* qis_t = sm + F_QT;
    float* w2s   = sm + F_W2;

    int b  = blockIdx.x >> 4;
    int i0 = (blockIdx.x & 15) * IPB;    // == r0 for proj phase
    int t  = threadIdx.x;

    // =======================================================================
    // PROJ PHASE: this block computes E_q for rows i0..i0+16 (kept in smem)
    // and E_k for the same 16 rows (written to global for all blocks of b).
    // Thread map: k = t>>4 (0..63), r = t&15.
    // =======================================================================
    {
        float* xs = sm + P_XS;
        float* ws = sm + P_WS;

        // stage x tile (padded rows): 1024 float4, one each
        {
            float4* xs4 = (float4*)xs;
            const float4* xg = (const float4*)(x + (b * LL + i0) * DD);
            int row = t >> 6, c4 = t & 63;
            xs4[row * (XPAD / 4) + c4] = __ldg(xg + t);
        }
        // stage ALL of W1: 8192 float4, 8 each (coalesced)
        {
            float4* ws4 = (float4*)ws;
            const float4* wg = (const float4*)W1;
            #pragma unroll
            for (int u = t; u < KK * 2 * DD / 4; u += 1024) ws4[u] = __ldg(wg + u);
        }
        if (t < KK) w2s[t] = (2.0f * LOG2E) * W2[t];
        __syncthreads();

        int k = t >> 4;
        int r = t & 15;

        const ulonglong2* xa = (const ulonglong2*)(xs + r * XPAD);
        const ulonglong2* wi = (const ulonglong2*)(ws + k * 2 * DD);
        const ulonglong2* wj = (const ulonglong2*)(ws + k * 2 * DD + DD);

        unsigned long long aq0 = 0ull, aq1 = 0ull, ak0 = 0ull, ak1 = 0ull;
        #pragma unroll 8
        for (int d4 = 0; d4 < DD / 4; d4++) {
            ulonglong2 xv  = xa[d4];
            ulonglong2 wiv = wi[d4];
            ulonglong2 wjv = wj[d4];
            aq0 = fma2u(xv.x, wiv.x, aq0);
            aq1 = fma2u(xv.y, wiv.y, aq1);
            ak0 = fma2u(xv.x, wjv.x, ak0);
            ak1 = fma2u(xv.y, wjv.y, ak1);
        }
        float2 f;
        float qs, ks;
        f = u2f2(aq0); qs  = f.x + f.y;
        f = u2f2(aq1); qs += f.x + f.y;
        f = u2f2(ak0); ks  = f.x + f.y;
        f = u2f2(ak1); ks += f.x + f.y;

        float eq = fast_ex2(qs * TANH_C);
        float ek = fast_ex2(ks * TANH_C);

        qis_t[k * IPB + r] = eq;                       // block-local E_q tile
        g_kjE[(b * LL + i0 + r) * KK + k] = ek;        // global E_k rows
    }

    // =======================================================================
    // GRID BARRIER (monotonic counter; self-resetting across graph replays)
    // =======================================================================
    __threadfence();
    __syncthreads();
    if (t == 0) {
        unsigned my = atomicAdd(&g_bar, 1u) + 1u;
        unsigned target = ((my + GRID - 1u) / GRID) * GRID;
        while (*(volatile unsigned*)&g_bar < target) __nanosleep(32);
    }
    __syncthreads();

    // =======================================================================
    // ATTN PHASE
    // =======================================================================
    float* kjs     = sm + A_KJ;
    float* scoresS = sm + A_SC;
    float* attnT   = sm + A_AT;

    int tj = t & 255;
    int q  = t >> 8;     // quarter

    // stage E_k slab [j][k] padded to KROW
    {
        const float4* kg = (const float4*)(g_kjE + b * LL * KK);
        #pragma unroll
        for (int u = t; u < LL * KK / 4; u += 1024) {
            int j = u >> 4, k4 = u & 15;
            *(float4*)(kjs + j * KROW + k4 * 4) = __ldg(kg + u);
        }
    }
    __syncthreads();

    // ---- Phase A: 4 i's per thread; 1 rcp / 4 elems; no ex2; eq via LDS.128 ----
    float acc0 = 0.f, acc1 = 0.f, acc2 = 0.f, acc3 = 0.f;
    const float* qt = qis_t + q * 4;
    const float* ekrow = kjs + tj * KROW;
    unsigned long long one2 = dupf(1.0f);

    #pragma unroll
    for (int kb = 0; kb < KK / 4; kb++) {
        float4 ek4 = *(const float4*)(ekrow + kb * 4);
        #pragma unroll
        for (int u = 0; u < 4; u++) {
            int k = kb * 4 + u;
            float ekv = (u == 0) ? ek4.x : (u == 1) ? ek4.y : (u == 2) ? ek4.z : ek4.w;
            ulonglong2 eqp = *(const ulonglong2*)(qt + k * IPB);   // 1 LDS.128
            unsigned long long ekd = dupf(ekv);
            unsigned long long d01 = fma2u(eqp.x, ekd, one2);
            unsigned long long d23 = fma2u(eqp.y, ekd, one2);
            float2 D01 = u2f2(d01), D23 = u2f2(d23);
            float p01 = D01.x * D01.y;
            float p23 = D23.x * D23.y;
            float P   = p01 * p23;
            float r   = fast_rcp(P);
            float w   = w2s[k];
            float wr01 = w * (r * p23);   // = w/(d0*d1)
            float wr23 = w * (r * p01);   // = w/(d2*d3)
            acc0 = fmaf(wr01, D01.y, acc0);
            acc1 = fmaf(wr01, D01.x, acc1);
            acc2 = fmaf(wr23, D23.y, acc2);
            acc3 = fmaf(wr23, D23.x, acc3);
        }
    }
    // log2-domain score' = -sum(w'/d); const term dropped (softmax-invariant)
    scoresS[(q * 4 + 0) * LL + tj] = -acc0;
    scoresS[(q * 4 + 1) * LL + tj] = -acc1;
    scoresS[(q * 4 + 2) * LL + tj] = -acc2;
    scoresS[(q * 4 + 3) * LL + tj] = -acc3;
    __syncthreads();

    // ---- Phase B: softmax over j (log2 domain -> bare ex2) ----
    if (t < 512) {
        int w = t >> 5, lane = t & 31;
        float v[8];
        float mx = -1e30f;
        #pragma unroll
        for (int r = 0; r < 8; r++) {
            v[r] = scoresS[w * LL + lane + 32 * r];
            mx = fmaxf(mx, v[r]);
        }
        #pragma unroll
        for (int o = 16; o; o >>= 1) mx = fmaxf(mx, __shfl_xor_sync(0xffffffffu, mx, o));
        float s = 0.f;
        #pragma unroll
        for (int r = 0; r < 8; r++) { v[r] = fast_ex2(v[r] - mx); s += v[r]; }
        #pragma unroll
        for (int o = 16; o; o >>= 1) s += __shfl_xor_sync(0xffffffffu, s, o);
        float inv = 1.f / s;
        #pragma unroll
        for (int r = 0; r < 8; r++)
            attnT[(lane + 32 * r) * IPB + w] = v[r] * inv;
    }
    __syncthreads();

    // ---- Phase C: all 16 i's (8 packed pairs) over this quarter's 64 j ----
    unsigned long long a[8];
    #pragma unroll
    for (int p = 0; p < 8; p++) a[p] = 0ull;

    const float* xb = x + b * LL * DD;
    {
        const float* xc = xb + tj;
        int jb = q * 64;
        #pragma unroll 8
        for (int j = 0; j < 64; j++) {
            int jj = jb + j;
            float xv = __ldg(xc + jj * DD);
            unsigned long long xx = dupf(xv);
            const ulonglong2* atp = (const ulonglong2*)(attnT + jj * IPB);
            ulonglong2 q0 = atp[0], q1 = atp[1];
            a[0] = fma2u(q0.x, xx, a[0]);
            a[1] = fma2u(q0.y, xx, a[1]);
            a[2] = fma2u(q1.x, xx, a[2]);
            a[3] = fma2u(q1.y, xx, a[3]);
            ulonglong2 q2 = atp[2], q3 = atp[3];
            a[4] = fma2u(q2.x, xx, a[4]);
            a[5] = fma2u(q2.y, xx, a[5]);
            a[6] = fma2u(q3.x, xx, a[6]);
            a[7] = fma2u(q3.y, xx, a[7]);
        }
    }

    // partials -> smem (reuse slab: 32 rows x 256 ull = 64 KB <= slab size)
    unsigned long long* red = (unsigned long long*)kjs;
    #pragma unroll
    for (int p = 0; p < 8; p++) red[(q * 8 + p) * LL + tj] = a[p];
    __syncthreads();

    // quarter q reduces pairs {2q, 2q+1} and writes ctx; also copies 4 x-rows
    #pragma unroll
    for (int pp = 0; pp < 2; pp++) {
        int p = q * 2 + pp;
        unsigned long long s = red[p * LL + tj];
        s = add2u(s, red[(8 + p) * LL + tj]);
        s = add2u(s, red[(16 + p) * LL + tj]);
        s = add2u(s, red[(24 + p) * LL + tj]);
        float2 c = u2f2(s);
        out[(unsigned)(b * LL + i0 + 2 * p) * (2 * DD) + DD + tj]     = c.x;
        out[(unsigned)(b * LL + i0 + 2 * p + 1) * (2 * DD) + DD + tj] = c.y;
    }
    #pragma unroll
    for (int r = 0; r < 4; r++) {
        int i = q * 4 + r;
        out[(unsigned)(b * LL + i0 + i) * (2 * DD) + tj] =
            __ldg(xb + (i0 + i) * DD + tj);
    }
}

// ---------------------------------------------------------------------------
extern "C" void kernel_launch(void* const* d_in, const int* in_sizes, int n_in,
                              void* d_out, int out_size) {
    const float* x  = (const float*)d_in[0];   // (8,256,256)
    const float* W1 = (const float*)d_in[1];   // (64,512)
    const float* W2 = (const float*)d_in[2];   // (1,64)
    float* out = (float*)d_out;                // (8,256,512)

    cudaFuncSetAttribute(fused_kernel,
                         cudaFuncAttributeMaxDynamicSharedMemorySize,
                         SMEM_BYTES);
    fused_kernel<<<GRID, 1024, SMEM_BYTES>>>(x, W1, W2, out);
}